// round 14
// baseline (speedup 1.0000x reference)
#include <cuda_runtime.h>
#include <cuda_bf16.h>
#include <cstdint>
#include <math.h>

#define NB 32
#define NN 512
#define DD 256
#define INV_EPS 10.0f
#define TINYF 1e-16f
#define MARG (1.0f/512.0f)
#define ITERS 15
#define PGRID 128      // 32 clusters x 4 CTAs; 1 block/SM
#define PTHREADS 512

// ---------------- helpers -----------------------------------------------------
__device__ __forceinline__ unsigned smem_u32(const void* p) {
    unsigned a;
    asm("{ .reg .u64 t; cvta.to.shared.u64 t, %1; cvt.u32.u64 %0, t; }"
        : "=r"(a) : "l"(p));
    return a;
}
__device__ __forceinline__ float dsmem_ld(unsigned local_addr, unsigned rank) {
    unsigned rem; float v;
    asm volatile("mapa.shared::cluster.u32 %0, %1, %2;" : "=r"(rem)
                 : "r"(local_addr), "r"(rank));
    asm volatile("ld.shared::cluster.f32 %0, [%1];" : "=f"(v) : "r"(rem));
    return v;
}
__device__ __forceinline__ void cp16(unsigned saddr, const void* g) {
    asm volatile("cp.async.ca.shared.global [%0], [%1], 16;"
                 :: "r"(saddr), "l"(g) : "memory");
}
#define CP_COMMIT() asm volatile("cp.async.commit_group;" ::: "memory")
#define CP_WAIT0()  asm volatile("cp.async.wait_group 0;" ::: "memory")
#define CP_WAIT1()  asm volatile("cp.async.wait_group 1;" ::: "memory")
#define CLUSTER_BAR() do { \
    asm volatile("barrier.cluster.arrive.aligned;" ::: "memory"); \
    asm volatile("barrier.cluster.wait.aligned;"   ::: "memory"); } while (0)

// ---------------- smem layout -------------------------------------------------
#define SM_E     0                            // 128KB: E tile, bf16x2 words
#define SM_COLP  131072                       // iter: [16][512] col partials
#define SM_COLR  (SM_COLP + 32768)            // iter: [2][512] double buffer
#define SM_AS0   SM_COLP                      // gemm: As0[128][36] f32 18432B
#define SM_AS1   (SM_COLP + 18432)            // gemm: As1 (covers colr too)
#define SM_W     (SM_COLR + 4096)             // iter: w[512]; pre-pass: ryAll[512]
#define SM_Q     (SM_W + 2048)
#define SM_P     (SM_Q + 2048)
#define SM_SU    (SM_P + 512)                 // gemm: rx[128]
#define SM_CRED  (SM_SU + 512)
#define SM_MISC_END (SM_CRED + 64 + 64)
#define SM_BS0   SM_MISC_END                  // gemm: Bs0[128][36]
#define SM_BS1   (SM_BS0 + 18432)
#define SM_TOT   (SM_BS1 + 18432)             // ~205 KB

// ---------------- fused kernel: GEMM + Sinkhorn + epilogue -------------------
__global__ void __cluster_dims__(4, 1, 1) __launch_bounds__(PTHREADS, 1)
sink_kernel(float* __restrict__ cost, float* __restrict__ pi,
            float* __restrict__ C,
            const float* __restrict__ x, const float* __restrict__ y) {
    extern __shared__ unsigned char sm[];
    unsigned* Eu  = (unsigned*)(sm + SM_E);      // [128][256] words (2 bf16/word)
    float* colp   = (float*)(sm + SM_COLP);      // [16][512]
    float* colr   = (float*)(sm + SM_COLR);      // [2][512]
    float* w      = (float*)(sm + SM_W);         // [512]
    float* q      = (float*)(sm + SM_Q);         // [512]
    float* p      = (float*)(sm + SM_P);         // [128]
    float* su     = (float*)(sm + SM_SU);        // [128]  (gemm: rx)
    float* cred   = (float*)(sm + SM_CRED);      // [16]
    float* rxs    = su;
    float* ryAll  = w;                           // 512 y-norms during gemm

    int g = blockIdx.x, b = g >> 2;
    unsigned rank;
    asm("mov.u32 %0, %%cluster_ctarank;" : "=r"(rank));
    int row0 = (int)rank * 128;
    int t = threadIdx.x, warp = t >> 5, lane = t & 31;
    unsigned sb = smem_u32(sm);

    // ================= Phase 0: row norms (x local; y exchanged) ============
    if (t < 256) {
        int r = t & 127;
        const float4* row = (const float4*)
            ((t < 128 ? x : y) + ((size_t)(b*NN + row0 + r)) * DD);
        float s0 = 0.f, s1 = 0.f;
        #pragma unroll
        for (int j = 0; j < 32; j++) {
            float4 v0 = row[2*j], v1 = row[2*j+1];
            s0 += v0.x*v0.x + v0.y*v0.y + v0.z*v0.z + v0.w*v0.w;
            s1 += v1.x*v1.x + v1.y*v1.y + v1.z*v1.z + v1.w*v1.w;
        }
        float r2 = rsqrtf(s0 + s1);
        if (t < 128) rxs[r] = r2;
        else         colr[r] = r2;               // stage local y-norm slice
    }
    __syncthreads();
    CLUSTER_BAR();
    // gather all 512 y norms via DSMEM
    ryAll[t < 512 ? t : 0] = dsmem_ld(sb + SM_COLR + (unsigned)(t & 127) * 4,
                                      (unsigned)(t >> 7));
    CLUSTER_BAR();   // protect colr slices until every CTA has read them

    // ================= Phase 1: GEMM (tile 128x512, cp.async pipelined) =====
    {
        int wm = (warp >> 2) * 32;               // warp m offset 0..96
        int wn = (warp & 3) * 32;                // warp n offset 0..96
        int arow = t >> 2;                       // 0..127 staging row
        int ac8  = (t & 3) * 8;                  // staging col chunk (floats)
        const float* xrow = x + ((size_t)(b*NN + row0 + arow)) * DD;
        unsigned soff = (unsigned)(arow * 144 + ac8 * 4);   // byte offset in buf
        unsigned asb[2] = { sb + SM_AS0, sb + SM_AS1 };
        unsigned bsb[2] = { sb + SM_BS0, sb + SM_BS1 };

        for (int nt0 = 0; nt0 < 4; nt0++) {
            int n0 = nt0 * 128;
            const float* yrow = y + ((size_t)(b*NN + n0 + arow)) * DD;

            float acc[2][4][4];
            #pragma unroll
            for (int i=0;i<2;i++)
                #pragma unroll
                for (int j=0;j<4;j++)
                    #pragma unroll
                    for (int k=0;k<4;k++) acc[i][j][k] = 0.f;

            // prefetch slab 0
            cp16(asb[0] + soff,      xrow + ac8);
            cp16(asb[0] + soff + 16, xrow + ac8 + 4);
            cp16(bsb[0] + soff,      yrow + ac8);
            cp16(bsb[0] + soff + 16, yrow + ac8 + 4);
            CP_COMMIT();

            for (int s = 0; s < 8; s++) {
                if (s < 7) {
                    int k0 = (s + 1) * 32;
                    int nb = (s + 1) & 1;
                    cp16(asb[nb] + soff,      xrow + k0 + ac8);
                    cp16(asb[nb] + soff + 16, xrow + k0 + ac8 + 4);
                    cp16(bsb[nb] + soff,      yrow + k0 + ac8);
                    cp16(bsb[nb] + soff + 16, yrow + k0 + ac8 + 4);
                    CP_COMMIT();
                    CP_WAIT1();
                } else {
                    CP_WAIT0();
                }
                __syncthreads();
                float (*As)[36] = (float(*)[36])(sm + ((s & 1) ? SM_AS1 : SM_AS0));
                float (*Bs)[36] = (float(*)[36])(sm + ((s & 1) ? SM_BS1 : SM_BS0));
                #pragma unroll
                for (int ks = 0; ks < 4; ks++) {
                    int kc = ks * 8 + (lane & 3);
                    unsigned bf[4][2];
                    #pragma unroll
                    for (int nx = 0; nx < 4; nx++) {
                        int nbr = wn + nx*8 + (lane >> 2);
                        bf[nx][0] = __float_as_uint(Bs[nbr][kc]);
                        bf[nx][1] = __float_as_uint(Bs[nbr][kc + 4]);
                    }
                    #pragma unroll
                    for (int mt = 0; mt < 2; mt++) {
                        int ma = wm + mt*16 + (lane >> 2);
                        unsigned fa0 = __float_as_uint(As[ma    ][kc]);
                        unsigned fa1 = __float_as_uint(As[ma + 8][kc]);
                        unsigned fa2 = __float_as_uint(As[ma    ][kc + 4]);
                        unsigned fa3 = __float_as_uint(As[ma + 8][kc + 4]);
                        #pragma unroll
                        for (int nx = 0; nx < 4; nx++) {
                            asm volatile(
                                "mma.sync.aligned.m16n8k8.row.col.f32.tf32.tf32.f32 "
                                "{%0,%1,%2,%3}, {%4,%5,%6,%7}, {%8,%9}, {%0,%1,%2,%3};"
                                : "+f"(acc[mt][nx][0]), "+f"(acc[mt][nx][1]),
                                  "+f"(acc[mt][nx][2]), "+f"(acc[mt][nx][3])
                                : "r"(fa0), "r"(fa1), "r"(fa2), "r"(fa3),
                                  "r"(bf[nx][0]), "r"(bf[nx][1]));
                        }
                    }
                }
                __syncthreads();
            }
            // epilogue: C fp32 -> gmem, E bf16 -> smem Eu
            size_t cb = (size_t)b * NN * NN + (size_t)(row0) * NN;
            #pragma unroll
            for (int mt = 0; mt < 2; mt++) {
                #pragma unroll
                for (int nx = 0; nx < 4; nx++) {
                    int ml = wm + mt*16 + (lane >> 2);
                    int nl = wn + nx*8 + (lane & 3)*2;
                    float rx0 = rxs[ml], rx2 = rxs[ml + 8];
                    float ry0 = ryAll[n0 + nl], ry1 = ryAll[n0 + nl + 1];
                    float c0 = 1.0f - acc[mt][nx][0] * rx0 * ry0;
                    float c1 = 1.0f - acc[mt][nx][1] * rx0 * ry1;
                    float c2 = 1.0f - acc[mt][nx][2] * rx2 * ry0;
                    float c3 = 1.0f - acc[mt][nx][3] * rx2 * ry1;
                    *(float2*)&C[cb + (size_t)ml*NN + n0 + nl]     = make_float2(c0, c1);
                    *(float2*)&C[cb + (size_t)(ml+8)*NN + n0 + nl] = make_float2(c2, c3);
                    __nv_bfloat162 e01 = __floats2bfloat162_rn(__expf(-INV_EPS*c0), __expf(-INV_EPS*c1));
                    __nv_bfloat162 e23 = __floats2bfloat162_rn(__expf(-INV_EPS*c2), __expf(-INV_EPS*c3));
                    Eu[ml*256 + ((n0 + nl) >> 1)]     = *(unsigned*)&e01;
                    Eu[(ml+8)*256 + ((n0 + nl) >> 1)] = *(unsigned*)&e23;
                }
            }
            __syncthreads();
        }
    }

    // ================= Phase 2: Sinkhorn iterations ==========================
    if (t < 512) { w[t] = 1.f; q[t] = 1.f; }
    if (t < 128) p[t] = 1.f;
    __syncthreads();

    for (int it = 0; it < ITERS; it++) {
        float wreg[16];
        #pragma unroll
        for (int k = 0; k < 8; k++) {
            float2 wp = *(const float2*)&w[2*lane + 64*k];
            wreg[2*k] = wp.x; wreg[2*k+1] = wp.y;
        }
        float colacc[16];
        #pragma unroll
        for (int i = 0; i < 16; i++) colacc[i] = 0.f;

        #pragma unroll
        for (int rg = 0; rg < 4; rg++) {
            int rowA = warp * 8 + rg * 2;
            int rowB = rowA + 1;
            const unsigned* EA = &Eu[rowA * 256];
            const unsigned* EB = &Eu[rowB * 256];
            unsigned ea[8], eb[8];
            #pragma unroll
            for (int k = 0; k < 8; k++) ea[k] = EA[lane + 32*k];
            #pragma unroll
            for (int k = 0; k < 8; k++) eb[k] = EB[lane + 32*k];

            float dA0=0.f, dA1=0.f, dB0=0.f, dB1=0.f;
            #pragma unroll
            for (int k = 0; k < 8; k++) {
                dA0 += __uint_as_float(ea[k] << 16)         * wreg[2*k];
                dA1 += __uint_as_float(ea[k] & 0xffff0000u) * wreg[2*k+1];
                dB0 += __uint_as_float(eb[k] << 16)         * wreg[2*k];
                dB1 += __uint_as_float(eb[k] & 0xffff0000u) * wreg[2*k+1];
            }
            float dA = dA0 + dA1, dB = dB0 + dB1;
            #pragma unroll
            for (int o = 16; o; o >>= 1) {
                dA += __shfl_xor_sync(0xffffffffu, dA, o);
                dB += __shfl_xor_sync(0xffffffffu, dB, o);
            }
            float pA = p[rowA], pB = p[rowB];
            float uA = MARG / (pA * dA + TINYF);
            float uB = MARG / (pB * dB + TINYF);
            float pnA = pA * uA, pnB = pB * uB;
            if (lane == 0) {
                p[rowA] = pnA; p[rowB] = pnB;
                if (it == ITERS - 1) { su[rowA] = uA * pnA; su[rowB] = uB * pnB; }
            }
            #pragma unroll
            for (int k = 0; k < 8; k++) {
                colacc[2*k]   += __uint_as_float(ea[k] << 16)         * pnA
                               + __uint_as_float(eb[k] << 16)         * pnB;
                colacc[2*k+1] += __uint_as_float(ea[k] & 0xffff0000u) * pnA
                               + __uint_as_float(eb[k] & 0xffff0000u) * pnB;
            }
        }
        #pragma unroll
        for (int k = 0; k < 8; k++)
            *(float2*)&colp[warp * 512 + 2*lane + 64*k] =
                make_float2(colacc[2*k], colacc[2*k+1]);
        __syncthreads();
        if (t < 512) {
            float s = 0.f;
            #pragma unroll
            for (int j = 0; j < 16; j++) s += colp[j * 512 + t];
            colr[(it & 1) * 512 + t] = s;
        }
        CLUSTER_BAR();
        if (t < 512) {
            unsigned addr = sb + SM_COLR + (unsigned)(it & 1) * 2048 + t * 4;
            float s0 = dsmem_ld(addr, 0);
            float s1 = dsmem_ld(addr, 1);
            float s2 = dsmem_ld(addr, 2);
            float s3 = dsmem_ld(addr, 3);
            float tot = (s0 + s1) + (s2 + s3);
            float qold = q[t];
            float v = MARG / (qold * tot + TINYF);
            float qn = qold * v;
            q[t] = qn;
            w[t] = qn * v;
        }
        __syncthreads();
    }

    // ================= Phase 3: pi + cost epilogue ===========================
    size_t base = ((size_t)b * NN + row0) * NN;
    float csum = 0.f;
    for (int r = 0; r < 8; r++) {
        int row = warp * 8 + r;
        float s_u = su[row];
        const float4* C4 = (const float4*)(C + base + (size_t)row * NN);
        float4*       P4 = (float4*)(pi + base + (size_t)row * NN);
        #pragma unroll
        for (int k = 0; k < 4; k++) {
            int idx = lane + 32*k;
            float4 cc = C4[idx];
            float4 wv = *(const float4*)&w[4*lane + 128*k];
            float4 pv;
            pv.x = __expf(-INV_EPS*cc.x) * s_u * wv.x;
            pv.y = __expf(-INV_EPS*cc.y) * s_u * wv.y;
            pv.z = __expf(-INV_EPS*cc.z) * s_u * wv.z;
            pv.w = __expf(-INV_EPS*cc.w) * s_u * wv.w;
            csum += pv.x*cc.x + pv.y*cc.y + pv.z*cc.z + pv.w*cc.w;
            asm volatile("st.global.cs.v4.f32 [%0], {%1,%2,%3,%4};"
                         :: "l"(P4 + idx), "f"(pv.x), "f"(pv.y), "f"(pv.z), "f"(pv.w)
                         : "memory");
        }
    }
    #pragma unroll
    for (int o = 16; o; o >>= 1) csum += __shfl_xor_sync(0xffffffffu, csum, o);
    if (lane == 0) cred[warp] = csum;
    __syncthreads();
    if (t == 0) {
        float s = 0.f;
        #pragma unroll
        for (int i = 0; i < 16; i++) s += cred[i];
        cred[0] = s;
    }
    CLUSTER_BAR();
    if (rank == 0 && t == 0) {
        unsigned addr = sb + SM_CRED;
        float s0 = dsmem_ld(addr, 0);
        float s1 = dsmem_ld(addr, 1);
        float s2 = dsmem_ld(addr, 2);
        float s3 = dsmem_ld(addr, 3);
        cost[b] = (s0 + s1) + (s2 + s3);
    }
    CLUSTER_BAR();
}

// ---------------- launch ------------------------------------------------------
extern "C" void kernel_launch(void* const* d_in, const int* in_sizes, int n_in,
                              void* d_out, int out_size) {
    const float* x = (const float*)d_in[0];
    const float* y = (const float*)d_in[1];
    float* out  = (float*)d_out;
    float* cost = out;
    float* pi   = out + NB;
    float* C    = out + NB + (size_t)NB * NN * NN;

    static int smem_set = 0;
    if (!smem_set) {
        cudaFuncSetAttribute(sink_kernel,
                             cudaFuncAttributeMaxDynamicSharedMemorySize, SM_TOT);
        smem_set = 1;
    }

    sink_kernel<<<PGRID, PTHREADS, SM_TOT>>>(cost, pi, C, x, y);
}

// round 15
// speedup vs baseline: 1.0386x; 1.0386x over previous
#include <cuda_runtime.h>
#include <cuda_bf16.h>
#include <cstdint>
#include <math.h>

#define NB 32
#define NN 512
#define DD 256
#define INV_EPS 10.0f
#define TINYF 1e-16f
#define MARG (1.0f/512.0f)
#define ITERS 15
#define PGRID 128      // 32 clusters x 4 CTAs; 1 block/SM
#define PTHREADS 512

// ---------------- helpers -----------------------------------------------------
__device__ __forceinline__ unsigned smem_u32(const void* p) {
    unsigned a;
    asm("{ .reg .u64 t; cvta.to.shared.u64 t, %1; cvt.u32.u64 %0, t; }"
        : "=r"(a) : "l"(p));
    return a;
}
__device__ __forceinline__ float dsmem_ld(unsigned local_addr, unsigned rank) {
    unsigned rem; float v;
    asm volatile("mapa.shared::cluster.u32 %0, %1, %2;" : "=r"(rem)
                 : "r"(local_addr), "r"(rank));
    asm volatile("ld.shared::cluster.f32 %0, [%1];" : "=f"(v) : "r"(rem));
    return v;
}
__device__ __forceinline__ unsigned f2tf32(float f) {
    unsigned r;
    asm("cvt.rna.tf32.f32 %0, %1;" : "=r"(r) : "f"(f));
    return r;
}
#define CLUSTER_BAR() do { \
    asm volatile("barrier.cluster.arrive.aligned;" ::: "memory"); \
    asm volatile("barrier.cluster.wait.aligned;"   ::: "memory"); } while (0)

// ---------------- smem layout -------------------------------------------------
#define SM_E     0                            // 128KB: E tile, bf16x2 words
#define SM_COLP  131072                       // iter: [16][512] col partials
#define SM_COLR  (SM_COLP + 32768)            // iter: [2][512] double buffer
#define SM_AS0   SM_COLP                      // gemm: As0[128][36] f32 18432B
#define SM_AS1   (SM_COLP + 18432)            // gemm: As1 (covers colr too)
#define SM_W     (SM_COLR + 4096)             // iter: w[512]; gemm: ryAll[512]
#define SM_Q     (SM_W + 2048)
#define SM_P     (SM_Q + 2048)
#define SM_SU    (SM_P + 512)                 // gemm: rx[128]
#define SM_CRED  (SM_SU + 512)
#define SM_MISC_END (SM_CRED + 64 + 64)
#define SM_BS0   SM_MISC_END                  // gemm: Bs0[128][36]
#define SM_BS1   (SM_BS0 + 18432)
#define SM_TOT   (SM_BS1 + 18432)             // ~205 KB

// ---------------- fused kernel: GEMM + Sinkhorn + epilogue -------------------
__global__ void __cluster_dims__(4, 1, 1) __launch_bounds__(PTHREADS, 1)
sink_kernel(float* __restrict__ cost, float* __restrict__ pi,
            float* __restrict__ C,
            const float* __restrict__ x, const float* __restrict__ y) {
    extern __shared__ unsigned char sm[];
    unsigned* Eu  = (unsigned*)(sm + SM_E);      // [128][256] words (2 bf16/word)
    float* colp   = (float*)(sm + SM_COLP);      // [16][512]
    float* colr   = (float*)(sm + SM_COLR);      // [2][512]
    float* w      = (float*)(sm + SM_W);         // [512]
    float* q      = (float*)(sm + SM_Q);         // [512]
    float* p      = (float*)(sm + SM_P);         // [128]
    float* su     = (float*)(sm + SM_SU);        // [128]  (gemm: rx)
    float* cred   = (float*)(sm + SM_CRED);      // [16]
    float* rxs    = su;
    float* ryAll  = w;                           // 512 y-norms during gemm

    int g = blockIdx.x, b = g >> 2;
    unsigned rank;
    asm("mov.u32 %0, %%cluster_ctarank;" : "=r"(rank));
    int row0 = (int)rank * 128;
    int t = threadIdx.x, warp = t >> 5, lane = t & 31;
    unsigned sb = smem_u32(sm);

    // ================= Phase 0: row norms (x local; y exchanged) ============
    if (t < 256) {
        int r = t & 127;
        const float4* row = (const float4*)
            ((t < 128 ? x : y) + ((size_t)(b*NN + row0 + r)) * DD);
        float s0 = 0.f, s1 = 0.f;
        #pragma unroll
        for (int j = 0; j < 32; j++) {
            float4 v0 = row[2*j], v1 = row[2*j+1];
            s0 += v0.x*v0.x + v0.y*v0.y + v0.z*v0.z + v0.w*v0.w;
            s1 += v1.x*v1.x + v1.y*v1.y + v1.z*v1.z + v1.w*v1.w;
        }
        float r2 = rsqrtf(s0 + s1);
        if (t < 128) rxs[r] = r2;
        else         colr[r] = r2;               // stage local y-norm slice
    }
    __syncthreads();
    CLUSTER_BAR();
    ryAll[t] = dsmem_ld(sb + SM_COLR + (unsigned)(t & 127) * 4,
                        (unsigned)(t >> 7));
    CLUSTER_BAR();   // protect colr slices until every CTA has read them

    // ================= Phase 1: GEMM (128x512, reg-prefetch pipelined) ======
    {
        int wm = (warp >> 2) * 32;               // warp m offset 0..96
        int wn = (warp & 3) * 32;                // warp n offset 0..96
        int arow = t >> 2;                       // 0..127 staging row
        int ac8  = (t & 3) * 8;                  // staging col chunk (floats)
        const float* xrow = x + ((size_t)(b*NN + row0 + arow)) * DD;

        for (int nt0 = 0; nt0 < 4; nt0++) {
            int n0 = nt0 * 128;
            const float* yrow = y + ((size_t)(b*NN + n0 + arow)) * DD;

            float acc[2][4][4];
            #pragma unroll
            for (int i=0;i<2;i++)
                #pragma unroll
                for (int j=0;j<4;j++)
                    #pragma unroll
                    for (int k=0;k<4;k++) acc[i][j][k] = 0.f;

            // prologue: load + stage slab 0
            float4 pa0 = *(const float4*)(xrow + ac8);
            float4 pa1 = *(const float4*)(xrow + ac8 + 4);
            float4 pb0 = *(const float4*)(yrow + ac8);
            float4 pb1 = *(const float4*)(yrow + ac8 + 4);
            {
                float (*As)[36] = (float(*)[36])(sm + SM_AS0);
                float (*Bs)[36] = (float(*)[36])(sm + SM_BS0);
                As[arow][ac8+0] = __uint_as_float(f2tf32(pa0.x));
                As[arow][ac8+1] = __uint_as_float(f2tf32(pa0.y));
                As[arow][ac8+2] = __uint_as_float(f2tf32(pa0.z));
                As[arow][ac8+3] = __uint_as_float(f2tf32(pa0.w));
                As[arow][ac8+4] = __uint_as_float(f2tf32(pa1.x));
                As[arow][ac8+5] = __uint_as_float(f2tf32(pa1.y));
                As[arow][ac8+6] = __uint_as_float(f2tf32(pa1.z));
                As[arow][ac8+7] = __uint_as_float(f2tf32(pa1.w));
                Bs[arow][ac8+0] = __uint_as_float(f2tf32(pb0.x));
                Bs[arow][ac8+1] = __uint_as_float(f2tf32(pb0.y));
                Bs[arow][ac8+2] = __uint_as_float(f2tf32(pb0.z));
                Bs[arow][ac8+3] = __uint_as_float(f2tf32(pb0.w));
                Bs[arow][ac8+4] = __uint_as_float(f2tf32(pb1.x));
                Bs[arow][ac8+5] = __uint_as_float(f2tf32(pb1.y));
                Bs[arow][ac8+6] = __uint_as_float(f2tf32(pb1.z));
                Bs[arow][ac8+7] = __uint_as_float(f2tf32(pb1.w));
            }
            __syncthreads();

            for (int s = 0; s < 8; s++) {
                // prefetch next slab into registers (latency hidden by mma)
                if (s < 7) {
                    int k0 = (s + 1) * 32;
                    pa0 = *(const float4*)(xrow + k0 + ac8);
                    pa1 = *(const float4*)(xrow + k0 + ac8 + 4);
                    pb0 = *(const float4*)(yrow + k0 + ac8);
                    pb1 = *(const float4*)(yrow + k0 + ac8 + 4);
                }
                float (*As)[36] = (float(*)[36])(sm + ((s & 1) ? SM_AS1 : SM_AS0));
                float (*Bs)[36] = (float(*)[36])(sm + ((s & 1) ? SM_BS1 : SM_BS0));
                #pragma unroll
                for (int ks = 0; ks < 4; ks++) {
                    int kc = ks * 8 + (lane & 3);
                    unsigned bf[4][2];
                    #pragma unroll
                    for (int nx = 0; nx < 4; nx++) {
                        int nbr = wn + nx*8 + (lane >> 2);
                        bf[nx][0] = __float_as_uint(Bs[nbr][kc]);
                        bf[nx][1] = __float_as_uint(Bs[nbr][kc + 4]);
                    }
                    #pragma unroll
                    for (int mt = 0; mt < 2; mt++) {
                        int ma = wm + mt*16 + (lane >> 2);
                        unsigned fa0 = __float_as_uint(As[ma    ][kc]);
                        unsigned fa1 = __float_as_uint(As[ma + 8][kc]);
                        unsigned fa2 = __float_as_uint(As[ma    ][kc + 4]);
                        unsigned fa3 = __float_as_uint(As[ma + 8][kc + 4]);
                        #pragma unroll
                        for (int nx = 0; nx < 4; nx++) {
                            asm volatile(
                                "mma.sync.aligned.m16n8k8.row.col.f32.tf32.tf32.f32 "
                                "{%0,%1,%2,%3}, {%4,%5,%6,%7}, {%8,%9}, {%0,%1,%2,%3};"
                                : "+f"(acc[mt][nx][0]), "+f"(acc[mt][nx][1]),
                                  "+f"(acc[mt][nx][2]), "+f"(acc[mt][nx][3])
                                : "r"(fa0), "r"(fa1), "r"(fa2), "r"(fa3),
                                  "r"(bf[nx][0]), "r"(bf[nx][1]));
                        }
                    }
                }
                __syncthreads();
                if (s < 7) {
                    float (*An)[36] = (float(*)[36])(sm + (((s+1) & 1) ? SM_AS1 : SM_AS0));
                    float (*Bn)[36] = (float(*)[36])(sm + (((s+1) & 1) ? SM_BS1 : SM_BS0));
                    An[arow][ac8+0] = __uint_as_float(f2tf32(pa0.x));
                    An[arow][ac8+1] = __uint_as_float(f2tf32(pa0.y));
                    An[arow][ac8+2] = __uint_as_float(f2tf32(pa0.z));
                    An[arow][ac8+3] = __uint_as_float(f2tf32(pa0.w));
                    An[arow][ac8+4] = __uint_as_float(f2tf32(pa1.x));
                    An[arow][ac8+5] = __uint_as_float(f2tf32(pa1.y));
                    An[arow][ac8+6] = __uint_as_float(f2tf32(pa1.z));
                    An[arow][ac8+7] = __uint_as_float(f2tf32(pa1.w));
                    Bn[arow][ac8+0] = __uint_as_float(f2tf32(pb0.x));
                    Bn[arow][ac8+1] = __uint_as_float(f2tf32(pb0.y));
                    Bn[arow][ac8+2] = __uint_as_float(f2tf32(pb0.z));
                    Bn[arow][ac8+3] = __uint_as_float(f2tf32(pb0.w));
                    Bn[arow][ac8+4] = __uint_as_float(f2tf32(pb1.x));
                    Bn[arow][ac8+5] = __uint_as_float(f2tf32(pb1.y));
                    Bn[arow][ac8+6] = __uint_as_float(f2tf32(pb1.z));
                    Bn[arow][ac8+7] = __uint_as_float(f2tf32(pb1.w));
                    __syncthreads();
                }
            }
            // epilogue: C fp32 -> gmem, E bf16 -> smem Eu
            size_t cb = (size_t)b * NN * NN + (size_t)(row0) * NN;
            #pragma unroll
            for (int mt = 0; mt < 2; mt++) {
                #pragma unroll
                for (int nx = 0; nx < 4; nx++) {
                    int ml = wm + mt*16 + (lane >> 2);
                    int nl = wn + nx*8 + (lane & 3)*2;
                    float rx0 = rxs[ml], rx2 = rxs[ml + 8];
                    float ry0 = ryAll[n0 + nl], ry1 = ryAll[n0 + nl + 1];
                    float c0 = 1.0f - acc[mt][nx][0] * rx0 * ry0;
                    float c1 = 1.0f - acc[mt][nx][1] * rx0 * ry1;
                    float c2 = 1.0f - acc[mt][nx][2] * rx2 * ry0;
                    float c3 = 1.0f - acc[mt][nx][3] * rx2 * ry1;
                    *(float2*)&C[cb + (size_t)ml*NN + n0 + nl]     = make_float2(c0, c1);
                    *(float2*)&C[cb + (size_t)(ml+8)*NN + n0 + nl] = make_float2(c2, c3);
                    __nv_bfloat162 e01 = __floats2bfloat162_rn(__expf(-INV_EPS*c0), __expf(-INV_EPS*c1));
                    __nv_bfloat162 e23 = __floats2bfloat162_rn(__expf(-INV_EPS*c2), __expf(-INV_EPS*c3));
                    Eu[ml*256 + ((n0 + nl) >> 1)]     = *(unsigned*)&e01;
                    Eu[(ml+8)*256 + ((n0 + nl) >> 1)] = *(unsigned*)&e23;
                }
            }
            __syncthreads();
        }
    }

    // ================= Phase 2: Sinkhorn iterations ==========================
    if (t < 512) { w[t] = 1.f; q[t] = 1.f; }
    if (t < 128) p[t] = 1.f;
    __syncthreads();

    for (int it = 0; it < ITERS; it++) {
        float wreg[16];
        #pragma unroll
        for (int k = 0; k < 8; k++) {
            float2 wp = *(const float2*)&w[2*lane + 64*k];
            wreg[2*k] = wp.x; wreg[2*k+1] = wp.y;
        }
        float colacc[16];
        #pragma unroll
        for (int i = 0; i < 16; i++) colacc[i] = 0.f;

        #pragma unroll
        for (int rg = 0; rg < 4; rg++) {
            int rowA = warp * 8 + rg * 2;
            int rowB = rowA + 1;
            const unsigned* EA = &Eu[rowA * 256];
            const unsigned* EB = &Eu[rowB * 256];
            unsigned ea[8], eb[8];
            #pragma unroll
            for (int k = 0; k < 8; k++) ea[k] = EA[lane + 32*k];
            #pragma unroll
            for (int k = 0; k < 8; k++) eb[k] = EB[lane + 32*k];

            float dA0=0.f, dA1=0.f, dB0=0.f, dB1=0.f;
            #pragma unroll
            for (int k = 0; k < 8; k++) {
                dA0 += __uint_as_float(ea[k] << 16)         * wreg[2*k];
                dA1 += __uint_as_float(ea[k] & 0xffff0000u) * wreg[2*k+1];
                dB0 += __uint_as_float(eb[k] << 16)         * wreg[2*k];
                dB1 += __uint_as_float(eb[k] & 0xffff0000u) * wreg[2*k+1];
            }
            float dA = dA0 + dA1, dB = dB0 + dB1;
            #pragma unroll
            for (int o = 16; o; o >>= 1) {
                dA += __shfl_xor_sync(0xffffffffu, dA, o);
                dB += __shfl_xor_sync(0xffffffffu, dB, o);
            }
            float pA = p[rowA], pB = p[rowB];
            float uA = MARG / (pA * dA + TINYF);
            float uB = MARG / (pB * dB + TINYF);
            float pnA = pA * uA, pnB = pB * uB;
            if (lane == 0) {
                p[rowA] = pnA; p[rowB] = pnB;
                if (it == ITERS - 1) { su[rowA] = uA * pnA; su[rowB] = uB * pnB; }
            }
            #pragma unroll
            for (int k = 0; k < 8; k++) {
                colacc[2*k]   += __uint_as_float(ea[k] << 16)         * pnA
                               + __uint_as_float(eb[k] << 16)         * pnB;
                colacc[2*k+1] += __uint_as_float(ea[k] & 0xffff0000u) * pnA
                               + __uint_as_float(eb[k] & 0xffff0000u) * pnB;
            }
        }
        #pragma unroll
        for (int k = 0; k < 8; k++)
            *(float2*)&colp[warp * 512 + 2*lane + 64*k] =
                make_float2(colacc[2*k], colacc[2*k+1]);
        __syncthreads();
        if (t < 512) {
            float s = 0.f;
            #pragma unroll
            for (int j = 0; j < 16; j++) s += colp[j * 512 + t];
            colr[(it & 1) * 512 + t] = s;
        }
        CLUSTER_BAR();
        if (t < 512) {
            unsigned addr = sb + SM_COLR + (unsigned)(it & 1) * 2048 + t * 4;
            float s0 = dsmem_ld(addr, 0);
            float s1 = dsmem_ld(addr, 1);
            float s2 = dsmem_ld(addr, 2);
            float s3 = dsmem_ld(addr, 3);
            float tot = (s0 + s1) + (s2 + s3);
            float qold = q[t];
            float v = MARG / (qold * tot + TINYF);
            float qn = qold * v;
            q[t] = qn;
            w[t] = qn * v;
        }
        __syncthreads();
    }

    // ================= Phase 3: pi + cost epilogue ===========================
    size_t base = ((size_t)b * NN + row0) * NN;
    float csum = 0.f;
    for (int r = 0; r < 8; r++) {
        int row = warp * 8 + r;
        float s_u = su[row];
        const float4* C4 = (const float4*)(C + base + (size_t)row * NN);
        float4*       P4 = (float4*)(pi + base + (size_t)row * NN);
        #pragma unroll
        for (int k = 0; k < 4; k++) {
            int idx = lane + 32*k;
            float4 cc = C4[idx];
            float4 wv = *(const float4*)&w[4*lane + 128*k];
            float4 pv;
            pv.x = __expf(-INV_EPS*cc.x) * s_u * wv.x;
            pv.y = __expf(-INV_EPS*cc.y) * s_u * wv.y;
            pv.z = __expf(-INV_EPS*cc.z) * s_u * wv.z;
            pv.w = __expf(-INV_EPS*cc.w) * s_u * wv.w;
            csum += pv.x*cc.x + pv.y*cc.y + pv.z*cc.z + pv.w*cc.w;
            asm volatile("st.global.cs.v4.f32 [%0], {%1,%2,%3,%4};"
                         :: "l"(P4 + idx), "f"(pv.x), "f"(pv.y), "f"(pv.z), "f"(pv.w)
                         : "memory");
        }
    }
    #pragma unroll
    for (int o = 16; o; o >>= 1) csum += __shfl_xor_sync(0xffffffffu, csum, o);
    if (lane == 0) cred[warp] = csum;
    __syncthreads();
    if (t == 0) {
        float s = 0.f;
        #pragma unroll
        for (int i = 0; i < 16; i++) s += cred[i];
        cred[0] = s;
    }
    CLUSTER_BAR();
    if (rank == 0 && t == 0) {
        unsigned addr = sb + SM_CRED;
        float s0 = dsmem_ld(addr, 0);
        float s1 = dsmem_ld(addr, 1);
        float s2 = dsmem_ld(addr, 2);
        float s3 = dsmem_ld(addr, 3);
        cost[b] = (s0 + s1) + (s2 + s3);
    }
    CLUSTER_BAR();
}

// ---------------- launch ------------------------------------------------------
extern "C" void kernel_launch(void* const* d_in, const int* in_sizes, int n_in,
                              void* d_out, int out_size) {
    const float* x = (const float*)d_in[0];
    const float* y = (const float*)d_in[1];
    float* out  = (float*)d_out;
    float* cost = out;
    float* pi   = out + NB;
    float* C    = out + NB + (size_t)NB * NN * NN;

    static int smem_set = 0;
    if (!smem_set) {
        cudaFuncSetAttribute(sink_kernel,
                             cudaFuncAttributeMaxDynamicSharedMemorySize, SM_TOT);
        smem_set = 1;
    }

    sink_kernel<<<PGRID, PTHREADS, SM_TOT>>>(cost, pi, C, x, y);
}